// round 1
// baseline (speedup 1.0000x reference)
#include <cuda_runtime.h>
#include <cuda_bf16.h>

// ---------------------------------------------------------------------------
// SecondOrderLatentSDE: two 2-layer MLPs + drift/diffusion epilogue.
//   pm  = z[:, :512], momentum = z[:, 256:512]
//   i   = min(searchsorted(ts, t, right), 15)
//   Hpost  = tanh([pm | ctx[:,i]] @ Wc1 + bc1)   (16384 x 1024)
//   Hprior = tanh(pm @ Wh1 + bh1)                (16384 x 1024)
//   post   = Hpost @ Wc2 + bc2                   (16384 x 256)
//   prior  = Hprior @ Wh2 + bh2                  (16384 x 256)
//   drift  = [inv_mass*momentum, post, sum(((prior-post)/diff)^2)]
//   diffusion_out = [0, diff, 0]
// Output = drift (B x 513) followed by diffusion_out (B x 513), fp32.
// ---------------------------------------------------------------------------

#define BATCH 16384
#define BM 128
#define BN 128
#define BK 16

// scratch (no allocations allowed -> __device__ globals)
__device__ float g_H[(size_t)2 * BATCH * 1024];  // Hpost then Hprior
__device__ float g_P[(size_t)BATCH * 512];       // post (0:256) | prior (256:512)

// ---- packed f32x2 helpers (Blackwell FFMA2 path, PTX-only) ----------------
__device__ __forceinline__ unsigned long long pack_dup(float x) {
    unsigned long long r;
    asm("mov.b64 %0, {%1, %1};" : "=l"(r) : "f"(x));
    return r;
}
__device__ __forceinline__ unsigned long long fma2(unsigned long long a,
                                                   unsigned long long b,
                                                   unsigned long long c) {
    unsigned long long d;
    asm("fma.rn.f32x2 %0, %1, %2, %3;" : "=l"(d) : "l"(a), "l"(b), "l"(c));
    return d;
}
__device__ __forceinline__ void unpack2(unsigned long long v, float& x, float& y) {
    asm("mov.b64 {%0, %1}, %2;" : "=f"(x), "=f"(y) : "l"(v));
}

// ---------------------------------------------------------------------------
// Generic fused GEMM: out[m,n] = act( sum_k A[m,k] * W[k,n] + bias[n] )
// A column k < split comes from A0 (row stride lda0);
// k >= split comes from ctx[:, i, :] (gather, row stride 16*512), where i is
// computed on-device from (ts, t).
// M = BATCH (grid.y * BM), N/K passed in, all divisible by tile sizes.
// ---------------------------------------------------------------------------
__global__ void __launch_bounds__(256)
gemm_kernel(const float* __restrict__ A0, long lda0,
            const float* __restrict__ ctx,
            const float* __restrict__ ts, const float* __restrict__ tp,
            const float* __restrict__ W,
            const float* __restrict__ bias,
            float* __restrict__ out, long ldo,
            int N, int K, int split, int doTanh)
{
    __shared__ float As[BK][BM];
    __shared__ float Bs[BK][BN];

    const int tid = threadIdx.x;
    const long bm = (long)blockIdx.y * BM;
    const long bn = (long)blockIdx.x * BN;

    // A-tile loader mapping: each thread loads 8 consecutive k of one row
    const int arow = tid >> 1;
    const int akg  = (tid & 1) * 8;
    // B-tile loader mapping: float4, fully coalesced
    const int brow = tid >> 5;
    const int bcol = (tid & 31) * 4;
    // compute mapping: 16x16 threads, 8x8 microtile
    const int tx = tid & 15;
    const int ty = tid >> 4;

    const float* a0r = A0 + (bm + arow) * lda0;
    const float* pA  = a0r + akg;
    const float* pB  = pA;  // safe default when no ctx gather
    if (ctx) {
        const float t = *tp;
        int cnt = 0;
        #pragma unroll
        for (int j = 0; j < 16; j++) cnt += (ts[j] <= t) ? 1 : 0;
        const int idx = cnt < 15 ? cnt : 15;
        // ctx is (B, 16, 512); row b slice = ctx + (b*16 + idx)*512
        pB = ctx + ((bm + arow) * 16 + idx) * 512 + akg - split;
    }

    float aR[8];
    float4 bR0, bR1;
    unsigned long long acc[8][4];
    #pragma unroll
    for (int i = 0; i < 8; i++)
        #pragma unroll
        for (int j = 0; j < 4; j++) acc[i][j] = 0ull;

    const int nk = K / BK;

    // ---- fetch tile kt into registers ----
    auto fetch = [&](int kt) {
        const int k0 = kt * BK;
        const float* src = ((k0 + akg) < split) ? pA : pB;
        #pragma unroll
        for (int j = 0; j < 8; j++) aR[j] = src[k0 + j];
        bR0 = *(const float4*)&W[(long)(k0 + brow) * N + bn + bcol];
        bR1 = *(const float4*)&W[(long)(k0 + brow + 8) * N + bn + bcol];
    };
    // ---- stage registers into smem ----
    auto stage = [&]() {
        #pragma unroll
        for (int j = 0; j < 8; j++) As[akg + j][arow] = aR[j];
        *(float4*)&Bs[brow][bcol]     = bR0;
        *(float4*)&Bs[brow + 8][bcol] = bR1;
    };

    fetch(0);
    stage();
    __syncthreads();

    for (int kt = 0; kt < nk; kt++) {
        if (kt + 1 < nk) fetch(kt + 1);

        #pragma unroll
        for (int kk = 0; kk < BK; kk++) {
            float4 av0 = *(const float4*)&As[kk][ty * 8];
            float4 av1 = *(const float4*)&As[kk][ty * 8 + 4];
            ulonglong2 bp0 = *(const ulonglong2*)&Bs[kk][tx * 8];
            ulonglong2 bp1 = *(const ulonglong2*)&Bs[kk][tx * 8 + 4];
            unsigned long long bq0 = bp0.x, bq1 = bp0.y, bq2 = bp1.x, bq3 = bp1.y;
            float av[8] = {av0.x, av0.y, av0.z, av0.w, av1.x, av1.y, av1.z, av1.w};
            #pragma unroll
            for (int i = 0; i < 8; i++) {
                unsigned long long ad = pack_dup(av[i]);
                acc[i][0] = fma2(ad, bq0, acc[i][0]);
                acc[i][1] = fma2(ad, bq1, acc[i][1]);
                acc[i][2] = fma2(ad, bq2, acc[i][2]);
                acc[i][3] = fma2(ad, bq3, acc[i][3]);
            }
        }
        __syncthreads();
        if (kt + 1 < nk) {
            stage();
            __syncthreads();
        }
    }

    // ---- epilogue: bias (+tanh), store ----
    #pragma unroll
    for (int i = 0; i < 8; i++) {
        const long row = bm + ty * 8 + i;
        #pragma unroll
        for (int jp = 0; jp < 4; jp++) {
            const long col = bn + tx * 8 + jp * 2;
            float x, y;
            unpack2(acc[i][jp], x, y);
            x += __ldg(&bias[col]);
            y += __ldg(&bias[col + 1]);
            if (doTanh) { x = tanhf(x); y = tanhf(y); }
            float2 v = make_float2(x, y);
            *(float2*)&out[row * ldo + col] = v;
        }
    }
}

// ---------------------------------------------------------------------------
// Epilogue: one warp per batch row.
// ---------------------------------------------------------------------------
__global__ void __launch_bounds__(256)
epilogue_kernel(const float* __restrict__ z,
                const float* __restrict__ P,
                const float* __restrict__ inv_mass,
                const float* __restrict__ diffusion,
                float* __restrict__ out)
{
    const int warp = threadIdx.x >> 5;
    const int lane = threadIdx.x & 31;
    const long b = (long)blockIdx.x * 8 + warp;
    if (b >= BATCH) return;

    const float* prow  = P + b * 512;
    float* drift = out + b * 513;
    float* dout  = out + (long)BATCH * 513 + b * 513;

    float local = 0.f;
    #pragma unroll
    for (int jj = 0; jj < 8; jj++) {
        const int n = jj * 32 + lane;
        const float post  = prow[n];
        const float prior = prow[256 + n];
        const float d = diffusion[n];
        // safe_divide semantics
        const float sgn = (d > 0.f) ? 1.f : ((d < 0.f) ? -1.f : 0.f);
        const float sd = (fabsf(d) > 1e-7f) ? d : sgn * 1e-7f;
        const float q = (prior - post) / sd;
        local += q * q;

        const float mom = z[b * 513 + 256 + n];
        drift[n]       = inv_mass[n] * mom;
        drift[256 + n] = post;
        dout[n]        = 0.f;
        dout[256 + n]  = d;
    }
    #pragma unroll
    for (int o = 16; o; o >>= 1) local += __shfl_xor_sync(0xffffffffu, local, o);
    if (lane == 0) {
        drift[512] = local;
        dout[512]  = 0.f;
    }
}

// ---------------------------------------------------------------------------
extern "C" void kernel_launch(void* const* d_in, const int* in_sizes, int n_in,
                              void* d_out, int out_size) {
    const float* z         = (const float*)d_in[0];
    const float* ts        = (const float*)d_in[1];
    const float* tp        = (const float*)d_in[2];
    const float* ctx       = (const float*)d_in[3];
    const float* inv_mass  = (const float*)d_in[4];
    const float* diffusion = (const float*)d_in[5];
    const float* Wc1       = (const float*)d_in[6];
    const float* bc1       = (const float*)d_in[7];
    const float* Wc2       = (const float*)d_in[8];
    const float* bc2       = (const float*)d_in[9];
    const float* Wh1       = (const float*)d_in[10];
    const float* bh1       = (const float*)d_in[11];
    const float* Wh2       = (const float*)d_in[12];
    const float* bh2       = (const float*)d_in[13];
    float* out = (float*)d_out;

    float *gH = nullptr, *gP = nullptr;
    cudaGetSymbolAddress((void**)&gH, g_H);
    cudaGetSymbolAddress((void**)&gP, g_P);
    float* gHpost  = gH;
    float* gHprior = gH + (size_t)BATCH * 1024;

    dim3 blk(256);
    dim3 grid1(1024 / BN, BATCH / BM);
    dim3 grid2(256 / BN, BATCH / BM);

    // Hpost = tanh([pm|ctx_i] @ Wc1 + bc1)
    gemm_kernel<<<grid1, blk>>>(z, 513, ctx, ts, tp, Wc1, bc1,
                                gHpost, 1024, 1024, 1024, 512, 1);
    // Hprior = tanh(pm @ Wh1 + bh1)
    gemm_kernel<<<grid1, blk>>>(z, 513, nullptr, ts, tp, Wh1, bh1,
                                gHprior, 1024, 1024, 512, 512, 1);
    // post = Hpost @ Wc2 + bc2
    gemm_kernel<<<grid2, blk>>>(gHpost, 1024, nullptr, ts, tp, Wc2, bc2,
                                gP, 512, 256, 1024, 1024, 0);
    // prior = Hprior @ Wh2 + bh2
    gemm_kernel<<<grid2, blk>>>(gHprior, 1024, nullptr, ts, tp, Wh2, bh2,
                                gP + 256, 512, 256, 1024, 1024, 0);
    // assemble outputs
    epilogue_kernel<<<BATCH / 8, 256>>>(z, gP, inv_mass, diffusion, out);
}

// round 4
// speedup vs baseline: 2.6914x; 2.6914x over previous
#include <cuda_runtime.h>
#include <cuda_bf16.h>
#include <cstdint>

// ===========================================================================
// SecondOrderLatentSDE via warp-level mma.sync bf16 (3-term fp32 emulation).
// tcgen05 is unavailable (harness assembles PTX at base target sm_103), but
// mma.sync.m16n8k16.bf16 / ldmatrix / cp.async are base sm_80+ instructions.
//
//   prep   : split [z|ctx_i] and z into bf16 hi/lo; split all W matrices.
//   L1post : Hpost = tanh([z|ctx_i] @ Wc1 + bc1)  -> stored split hi/lo
//   L1prior: Hprior= tanh(z @ Wh1 + bh1)          -> stored split hi/lo
//   L2 x2  : post/prior = H @ W2 + b2             -> fp32 P
//   epilogue assembles drift/diffusion outputs.
// ===========================================================================

#define BATCH 16384

// ---- global scratch (__device__; no allocations allowed) ----
__device__ __nv_bfloat16 g_Apost_hi[(size_t)BATCH * 1024];
__device__ __nv_bfloat16 g_Apost_lo[(size_t)BATCH * 1024];
__device__ __nv_bfloat16 g_Aprior_hi[(size_t)BATCH * 512];
__device__ __nv_bfloat16 g_Aprior_lo[(size_t)BATCH * 512];
__device__ __nv_bfloat16 g_H_hi[(size_t)2 * BATCH * 1024];   // Hpost | Hprior
__device__ __nv_bfloat16 g_H_lo[(size_t)2 * BATCH * 1024];
__device__ __nv_bfloat16 g_W_hi[1024 * 1024 + 512 * 1024 + 2 * 1024 * 256];
__device__ __nv_bfloat16 g_W_lo[1024 * 1024 + 512 * 1024 + 2 * 1024 * 256];
__device__ float g_P[(size_t)BATCH * 512];                   // post | prior

#define WOFF_C1 0
#define WOFF_H1 (1024 * 1024)
#define WOFF_C2 (1024 * 1024 + 512 * 1024)
#define WOFF_H2 (1024 * 1024 + 512 * 1024 + 1024 * 256)

// ---- smem geometry ----
#define PA 80                      // A row pitch bytes (32 bf16 + 8 pad)
#define PB 272                     // B row pitch bytes (128 bf16 + 8 pad)
#define ASZ (128 * PA)             // 10240
#define BSZ (32 * PB)              // 8704
#define STAGE (2 * ASZ + 2 * BSZ)  // 37888
#define SMEMB (2 * STAGE)          // 75776

// ===========================================================================
// PTX helpers (all base-target instructions)
// ===========================================================================
__device__ __forceinline__ uint32_t smem_u32(const void* p) {
    uint32_t a;
    asm("{ .reg .u64 t; cvta.to.shared.u64 t, %1; cvt.u32.u64 %0, t; }" : "=r"(a) : "l"(p));
    return a;
}
#define CP_ASYNC(dst, src) \
    asm volatile("cp.async.cg.shared.global [%0], [%1], 16;" :: "r"(dst), "l"(src))
#define CP_COMMIT() asm volatile("cp.async.commit_group;")
#define CP_WAIT(n)  asm volatile("cp.async.wait_group %0;" :: "n"(n))

__device__ __forceinline__ void ldsm_x4(uint32_t* r, uint32_t addr) {
    asm volatile("ldmatrix.sync.aligned.m8n8.x4.shared.b16 {%0,%1,%2,%3}, [%4];"
        : "=r"(r[0]), "=r"(r[1]), "=r"(r[2]), "=r"(r[3]) : "r"(addr));
}
__device__ __forceinline__ void ldsm_x4_t(uint32_t* r, uint32_t addr) {
    asm volatile("ldmatrix.sync.aligned.m8n8.x4.trans.shared.b16 {%0,%1,%2,%3}, [%4];"
        : "=r"(r[0]), "=r"(r[1]), "=r"(r[2]), "=r"(r[3]) : "r"(addr));
}
__device__ __forceinline__ void mma_bf16(float* d, const uint32_t* a, const uint32_t* b) {
    asm volatile("mma.sync.aligned.m16n8k16.row.col.f32.bf16.bf16.f32 "
        "{%0,%1,%2,%3}, {%4,%5,%6,%7}, {%8,%9}, {%0,%1,%2,%3};"
        : "+f"(d[0]), "+f"(d[1]), "+f"(d[2]), "+f"(d[3])
        : "r"(a[0]), "r"(a[1]), "r"(a[2]), "r"(a[3]), "r"(b[0]), "r"(b[1]));
}

// ===========================================================================
// prep kernels
// ===========================================================================
__global__ void __launch_bounds__(256)
prep_A(const float* __restrict__ z, const float* __restrict__ ctx,
       const float* __restrict__ ts, const float* __restrict__ tp,
       __nv_bfloat16* __restrict__ Aph, __nv_bfloat16* __restrict__ Apl,
       __nv_bfloat16* __restrict__ Arh, __nv_bfloat16* __restrict__ Arl)
{
    const float t = *tp;
    int cnt = 0;
#pragma unroll
    for (int j = 0; j < 16; j++) cnt += (ts[j] <= t) ? 1 : 0;
    const int idx = cnt < 15 ? cnt : 15;

    const size_t i = (size_t)blockIdx.x * blockDim.x + threadIdx.x;  // over B*1024
    const int row = (int)(i >> 10);
    const int col = (int)(i & 1023);
    float v;
    if (col < 512) v = z[(size_t)row * 513 + col];
    else           v = ctx[((size_t)row * 16 + idx) * 512 + col - 512];
    __nv_bfloat16 h = __float2bfloat16(v);
    __nv_bfloat16 l = __float2bfloat16(v - __bfloat162float(h));
    Aph[i] = h;
    Apl[i] = l;
    if (col < 512) {
        Arh[(size_t)row * 512 + col] = h;
        Arl[(size_t)row * 512 + col] = l;
    }
}

__global__ void __launch_bounds__(256)
prep_W(const float* __restrict__ src, int n,
       __nv_bfloat16* __restrict__ hi, __nv_bfloat16* __restrict__ lo)
{
    const int i = blockIdx.x * blockDim.x + threadIdx.x;
    if (i >= n) return;
    float v = src[i];
    __nv_bfloat16 h = __float2bfloat16(v);
    hi[i] = h;
    lo[i] = __float2bfloat16(v - __bfloat162float(h));
}

// ===========================================================================
// GEMM: C[128x128 tile] = Ahi@Whi + Alo@Whi + Ahi@Wlo  (+bias, opt tanh)
// MODE 0: tanh + re-split -> Hhi/Hlo (row stride 1024)
// MODE 1: fp32 + bias -> P (row stride 512, column offset poff)
// ===========================================================================
template <int MODE>
__global__ void __launch_bounds__(512, 1)
gemm_mma(const __nv_bfloat16* __restrict__ Ahi, const __nv_bfloat16* __restrict__ Alo, int K,
         const __nv_bfloat16* __restrict__ Whi, const __nv_bfloat16* __restrict__ Wlo, int ldw,
         const float* __restrict__ bias,
         __nv_bfloat16* __restrict__ Hhi, __nv_bfloat16* __restrict__ Hlo,
         float* __restrict__ P, int poff)
{
    extern __shared__ char smem[];
    const uint32_t sb = smem_u32(smem);
    const int tid = threadIdx.x;
    const size_t bm = (size_t)blockIdx.y * 128;
    const int bn = blockIdx.x * 128;

    // ---- cp.async loader mapping (4 x 16B chunks per thread) ----
    const int ar = tid >> 2, as = tid & 3;    // A: row 0..127, 16B seg 0..3
    const int br = tid >> 4, bs = tid & 15;   // B: k-row 0..31, seg 0..15
    const __nv_bfloat16* gAh = Ahi + (bm + ar) * (size_t)K + as * 8;
    const __nv_bfloat16* gAl = Alo + (bm + ar) * (size_t)K + as * 8;
    const __nv_bfloat16* gWh = Whi + (size_t)br * ldw + bn + bs * 8;
    const __nv_bfloat16* gWl = Wlo + (size_t)br * ldw + bn + bs * 8;
    const uint32_t sAo = ar * PA + as * 16;
    const uint32_t sBo = br * PB + bs * 16;

    // ---- compute mapping ----
    const int wid = tid >> 5, lane = tid & 31;
    const int wm = (wid >> 2) * 32;           // warp m offset (4 rows of warps)
    const int wn = (wid & 3) * 32;            // warp n offset
    // ldmatrix lane address bases
    const uint32_t aA = (wm + (lane & 15)) * PA + (lane >> 4) * 16;
    const uint32_t bA = (lane & 15) * PB + (wn + (lane >> 4) * 8) * 2;

    float acc[2][4][4];
#pragma unroll
    for (int a = 0; a < 2; a++)
#pragma unroll
        for (int b = 0; b < 4; b++)
#pragma unroll
            for (int c = 0; c < 4; c++) acc[a][b][c] = 0.f;

    const int NKT = K / 32;

    // stage loader
    auto load_stage = [&](int buf, int k0) {
        const uint32_t st = sb + buf * STAGE;
        CP_ASYNC(st + sAo,                 gAh + k0);
        CP_ASYNC(st + ASZ + sAo,           gAl + k0);
        CP_ASYNC(st + 2 * ASZ + sBo,       gWh + (size_t)k0 * ldw);
        CP_ASYNC(st + 2 * ASZ + BSZ + sBo, gWl + (size_t)k0 * ldw);
        CP_COMMIT();
    };

    load_stage(0, 0);

    for (int kt = 0; kt < NKT; kt++) {
        const int buf = kt & 1;
        __syncthreads();   // prev compute done before overwriting other buffer
        if (kt + 1 < NKT) {
            load_stage(buf ^ 1, (kt + 1) * 32);
            CP_WAIT(1);
        } else {
            CP_WAIT(0);
        }
        __syncthreads();   // stage data visible

        const uint32_t sA  = sb + buf * STAGE;
        const uint32_t sAl = sA + ASZ;
        const uint32_t sB  = sA + 2 * ASZ;
        const uint32_t sBl = sB + BSZ;

#pragma unroll
        for (int ks = 0; ks < 32; ks += 16) {
            uint32_t ah[2][4], al[2][4], bh[2][4], bl[2][4];
#pragma unroll
            for (int mt = 0; mt < 2; mt++) {
                ldsm_x4(ah[mt], sA  + aA + mt * 16 * PA + ks * 2);
                ldsm_x4(al[mt], sAl + aA + mt * 16 * PA + ks * 2);
            }
#pragma unroll
            for (int nt = 0; nt < 2; nt++) {
                ldsm_x4_t(bh[nt], sB  + bA + nt * 32 + ks * PB);
                ldsm_x4_t(bl[nt], sBl + bA + nt * 32 + ks * PB);
            }
#pragma unroll
            for (int mt = 0; mt < 2; mt++)
#pragma unroll
                for (int nb = 0; nb < 4; nb++) {
                    const uint32_t* B0 = &bh[nb >> 1][(nb & 1) * 2];
                    const uint32_t* L0 = &bl[nb >> 1][(nb & 1) * 2];
                    mma_bf16(acc[mt][nb], ah[mt], B0);
                    mma_bf16(acc[mt][nb], al[mt], B0);
                    mma_bf16(acc[mt][nb], ah[mt], L0);
                }
        }
    }

    // ---- epilogue ----
    const int g = lane >> 2, t4 = lane & 3;
#pragma unroll
    for (int mt = 0; mt < 2; mt++)
#pragma unroll
        for (int half = 0; half < 2; half++) {
            const size_t row = bm + wm + mt * 16 + g + half * 8;
#pragma unroll
            for (int nb = 0; nb < 4; nb++) {
                const int col = bn + wn + nb * 8 + t4 * 2;
                float x = acc[mt][nb][half * 2 + 0] + __ldg(&bias[col]);
                float y = acc[mt][nb][half * 2 + 1] + __ldg(&bias[col + 1]);
                if (MODE == 0) {
                    x = tanhf(x);
                    y = tanhf(y);
                    __nv_bfloat162 hb = __float22bfloat162_rn(make_float2(x, y));
                    float rx = x - __bfloat162float(hb.x);
                    float ry = y - __bfloat162float(hb.y);
                    __nv_bfloat162 lb = __float22bfloat162_rn(make_float2(rx, ry));
                    *(__nv_bfloat162*)&Hhi[row * 1024 + col] = hb;
                    *(__nv_bfloat162*)&Hlo[row * 1024 + col] = lb;
                } else {
                    *(float2*)&P[row * 512 + poff + col] = make_float2(x, y);
                }
            }
        }
}

// ===========================================================================
// Final assembly: one warp per batch row.
// ===========================================================================
__global__ void __launch_bounds__(256)
epilogue_kernel(const float* __restrict__ z, const float* __restrict__ P,
                const float* __restrict__ inv_mass, const float* __restrict__ diffusion,
                float* __restrict__ out)
{
    const int warp = threadIdx.x >> 5;
    const int lane = threadIdx.x & 31;
    const size_t b = (size_t)blockIdx.x * 8 + warp;
    if (b >= BATCH) return;

    const float* prow = P + b * 512;
    float* drift = out + b * 513;
    float* dout = out + (size_t)BATCH * 513 + b * 513;

    float local = 0.f;
#pragma unroll
    for (int jj = 0; jj < 8; jj++) {
        const int n = jj * 32 + lane;
        const float post = prow[n];
        const float prior = prow[256 + n];
        const float d = diffusion[n];
        const float sgn = (d > 0.f) ? 1.f : ((d < 0.f) ? -1.f : 0.f);
        const float sd = (fabsf(d) > 1e-7f) ? d : sgn * 1e-7f;
        const float q = (prior - post) / sd;
        local += q * q;

        drift[n] = inv_mass[n] * z[b * 513 + 256 + n];
        drift[256 + n] = post;
        dout[n] = 0.f;
        dout[256 + n] = d;
    }
#pragma unroll
    for (int o = 16; o; o >>= 1) local += __shfl_xor_sync(0xffffffffu, local, o);
    if (lane == 0) { drift[512] = local; dout[512] = 0.f; }
}

// ===========================================================================
extern "C" void kernel_launch(void* const* d_in, const int* in_sizes, int n_in,
                              void* d_out, int out_size) {
    const float* z         = (const float*)d_in[0];
    const float* ts        = (const float*)d_in[1];
    const float* tp        = (const float*)d_in[2];
    const float* ctx       = (const float*)d_in[3];
    const float* inv_mass  = (const float*)d_in[4];
    const float* diffusion = (const float*)d_in[5];
    const float* Wc1 = (const float*)d_in[6];
    const float* bc1 = (const float*)d_in[7];
    const float* Wc2 = (const float*)d_in[8];
    const float* bc2 = (const float*)d_in[9];
    const float* Wh1 = (const float*)d_in[10];
    const float* bh1 = (const float*)d_in[11];
    const float* Wh2 = (const float*)d_in[12];
    const float* bh2 = (const float*)d_in[13];
    float* out = (float*)d_out;

    __nv_bfloat16 *Aph, *Apl, *Arh, *Arl, *Hh, *Hl, *Wh, *Wl;
    float* gP;
    cudaGetSymbolAddress((void**)&Aph, g_Apost_hi);
    cudaGetSymbolAddress((void**)&Apl, g_Apost_lo);
    cudaGetSymbolAddress((void**)&Arh, g_Aprior_hi);
    cudaGetSymbolAddress((void**)&Arl, g_Aprior_lo);
    cudaGetSymbolAddress((void**)&Hh, g_H_hi);
    cudaGetSymbolAddress((void**)&Hl, g_H_lo);
    cudaGetSymbolAddress((void**)&Wh, g_W_hi);
    cudaGetSymbolAddress((void**)&Wl, g_W_lo);
    cudaGetSymbolAddress((void**)&gP, g_P);
    const size_t HO = (size_t)BATCH * 1024;

    static bool attr_done = false;
    if (!attr_done) {
        cudaFuncSetAttribute(gemm_mma<0>, cudaFuncAttributeMaxDynamicSharedMemorySize, SMEMB);
        cudaFuncSetAttribute(gemm_mma<1>, cudaFuncAttributeMaxDynamicSharedMemorySize, SMEMB);
        attr_done = true;
    }

    // ---- prep ----
    prep_A<<<(BATCH * 1024) / 256, 256>>>(z, ctx, ts, tp, Aph, Apl, Arh, Arl);
    prep_W<<<(1024 * 1024) / 256, 256>>>(Wc1, 1024 * 1024, Wh + WOFF_C1, Wl + WOFF_C1);
    prep_W<<<(512 * 1024) / 256, 256>>>(Wh1, 512 * 1024, Wh + WOFF_H1, Wl + WOFF_H1);
    prep_W<<<(1024 * 256) / 256, 256>>>(Wc2, 1024 * 256, Wh + WOFF_C2, Wl + WOFF_C2);
    prep_W<<<(1024 * 256) / 256, 256>>>(Wh2, 1024 * 256, Wh + WOFF_H2, Wl + WOFF_H2);

    // ---- GEMMs ----
    dim3 g1(8, BATCH / 128);   // N=1024
    dim3 g2(2, BATCH / 128);   // N=256

    // L1 post: Hpost = tanh([z|ctx] @ Wc1 + bc1)
    gemm_mma<0><<<g1, 512, SMEMB>>>(Aph, Apl, 1024, Wh + WOFF_C1, Wl + WOFF_C1, 1024,
                                    bc1, Hh, Hl, nullptr, 0);
    // L1 prior: Hprior = tanh(z @ Wh1 + bh1)
    gemm_mma<0><<<g1, 512, SMEMB>>>(Arh, Arl, 512, Wh + WOFF_H1, Wl + WOFF_H1, 1024,
                                    bh1, Hh + HO, Hl + HO, nullptr, 0);
    // L2 post: P[:, :256] = Hpost @ Wc2 + bc2
    gemm_mma<1><<<g2, 512, SMEMB>>>(Hh, Hl, 1024, Wh + WOFF_C2, Wl + WOFF_C2, 256,
                                    bc2, nullptr, nullptr, gP, 0);
    // L2 prior: P[:, 256:] = Hprior @ Wh2 + bh2
    gemm_mma<1><<<g2, 512, SMEMB>>>(Hh + HO, Hl + HO, 1024, Wh + WOFF_H2, Wl + WOFF_H2, 256,
                                    bh2, nullptr, nullptr, gP, 256);

    // ---- output assembly ----
    epilogue_kernel<<<BATCH / 8, 256>>>(z, gP, inv_mass, diffusion, out);
}

// round 5
// speedup vs baseline: 3.2488x; 1.2071x over previous
#include <cuda_runtime.h>
#include <cuda_bf16.h>
#include <cstdint>

// ===========================================================================
// SecondOrderLatentSDE via warp-level mma.sync bf16 (3-term fp32 emulation).
// CTA tile 128x256, warp tile 32x64, BK=32, 3-stage cp.async pipeline.
// ===========================================================================

#define BATCH 16384

// ---- global scratch ----
__device__ __nv_bfloat16 g_A_hi[(size_t)BATCH * 1024];   // [z | ctx_i] split
__device__ __nv_bfloat16 g_A_lo[(size_t)BATCH * 1024];
__device__ __nv_bfloat16 g_H_hi[(size_t)2 * BATCH * 1024];  // Hpost | Hprior
__device__ __nv_bfloat16 g_H_lo[(size_t)2 * BATCH * 1024];
__device__ __nv_bfloat16 g_W_hi[1024 * 1024 + 512 * 1024 + 2 * 1024 * 256];
__device__ __nv_bfloat16 g_W_lo[1024 * 1024 + 512 * 1024 + 2 * 1024 * 256];
__device__ float g_P[(size_t)BATCH * 512];               // post | prior

#define WOFF_C1 0
#define WOFF_H1 (1024 * 1024)
#define WOFF_C2 (1024 * 1024 + 512 * 1024)
#define WOFF_H2 (1024 * 1024 + 512 * 1024 + 1024 * 256)

// ---- smem geometry (3-stage ring) ----
#define PA 80                       // A row pitch: 64B data + 16 pad (odd 16B mult)
#define PB 528                      // B row pitch: 512B data + 16 pad (odd 16B mult)
#define ASZ (128 * PA)              // 10240
#define BSZ (32 * PB)               // 16896
#define STAGE (2 * ASZ + 2 * BSZ)   // 54272
#define NSTAGE 3
#define SMEMB (NSTAGE * STAGE)      // 162816

// ===========================================================================
__device__ __forceinline__ uint32_t smem_u32(const void* p) {
    uint32_t a;
    asm("{ .reg .u64 t; cvta.to.shared.u64 t, %1; cvt.u32.u64 %0, t; }" : "=r"(a) : "l"(p));
    return a;
}
#define CP_ASYNC(dst, src) \
    asm volatile("cp.async.cg.shared.global [%0], [%1], 16;" :: "r"(dst), "l"(src))
#define CP_COMMIT() asm volatile("cp.async.commit_group;")
#define CP_WAIT(n)  asm volatile("cp.async.wait_group %0;" :: "n"(n))

__device__ __forceinline__ void ldsm_x4(uint32_t* r, uint32_t addr) {
    asm volatile("ldmatrix.sync.aligned.m8n8.x4.shared.b16 {%0,%1,%2,%3}, [%4];"
        : "=r"(r[0]), "=r"(r[1]), "=r"(r[2]), "=r"(r[3]) : "r"(addr));
}
__device__ __forceinline__ void ldsm_x4_t(uint32_t* r, uint32_t addr) {
    asm volatile("ldmatrix.sync.aligned.m8n8.x4.trans.shared.b16 {%0,%1,%2,%3}, [%4];"
        : "=r"(r[0]), "=r"(r[1]), "=r"(r[2]), "=r"(r[3]) : "r"(addr));
}
__device__ __forceinline__ void mma_bf16(float* d, const uint32_t* a, const uint32_t* b) {
    asm volatile("mma.sync.aligned.m16n8k16.row.col.f32.bf16.bf16.f32 "
        "{%0,%1,%2,%3}, {%4,%5,%6,%7}, {%8,%9}, {%0,%1,%2,%3};"
        : "+f"(d[0]), "+f"(d[1]), "+f"(d[2]), "+f"(d[3])
        : "r"(a[0]), "r"(a[1]), "r"(a[2]), "r"(a[3]), "r"(b[0]), "r"(b[1]));
}

// ===========================================================================
// prep kernels
// ===========================================================================
__global__ void __launch_bounds__(256)
prep_A(const float* __restrict__ z, const float* __restrict__ ctx,
       const float* __restrict__ ts, const float* __restrict__ tp,
       __nv_bfloat16* __restrict__ Ah, __nv_bfloat16* __restrict__ Al)
{
    const float t = *tp;
    int cnt = 0;
#pragma unroll
    for (int j = 0; j < 16; j++) cnt += (ts[j] <= t) ? 1 : 0;
    const int idx = cnt < 15 ? cnt : 15;

    const size_t i = (size_t)blockIdx.x * blockDim.x + threadIdx.x;
    const int row = (int)(i >> 10);
    const int col = (int)(i & 1023);
    float v;
    if (col < 512) v = z[(size_t)row * 513 + col];
    else           v = ctx[((size_t)row * 16 + idx) * 512 + col - 512];
    __nv_bfloat16 h = __float2bfloat16(v);
    Ah[i] = h;
    Al[i] = __float2bfloat16(v - __bfloat162float(h));
}

__global__ void __launch_bounds__(256)
prep_W(const float* __restrict__ src, int n,
       __nv_bfloat16* __restrict__ hi, __nv_bfloat16* __restrict__ lo)
{
    const int i = blockIdx.x * blockDim.x + threadIdx.x;
    if (i >= n) return;
    float v = src[i];
    __nv_bfloat16 h = __float2bfloat16(v);
    hi[i] = h;
    lo[i] = __float2bfloat16(v - __bfloat162float(h));
}

// ===========================================================================
// GEMM: C = Ahi@Whi + Alo@Whi + Ahi@Wlo (+bias, opt tanh)
// CTA 128x256 (MODE1: 128x256 with bn=0, N=256), warp 32x64, BK=32.
// MODE 0: tanh + re-split -> Hhi/Hlo (row stride 1024)
// MODE 1: fp32 + bias -> P (row stride 512, column offset poff)
// ===========================================================================
template <int MODE>
__global__ void __launch_bounds__(512, 1)
gemm_mma(const __nv_bfloat16* __restrict__ Ahi, const __nv_bfloat16* __restrict__ Alo,
         int lda, int K,
         const __nv_bfloat16* __restrict__ Whi, const __nv_bfloat16* __restrict__ Wlo, int ldw,
         const float* __restrict__ bias,
         __nv_bfloat16* __restrict__ Hhi, __nv_bfloat16* __restrict__ Hlo,
         float* __restrict__ P, int poff)
{
    extern __shared__ char smem[];
    const uint32_t sb = smem_u32(smem);
    const int tid = threadIdx.x;
    const size_t bm = (size_t)blockIdx.y * 128;
    const int bn = blockIdx.x * 256;

    // ---- cp.async loader mapping ----
    const int ar = tid >> 2, as = tid & 3;     // A: row 0..127, 16B seg 0..3 (covers 32 k)
    const int br = tid >> 4, bs = tid & 15;    // B: k-row 0..31, 2 chunks per thread
    const __nv_bfloat16* gAh = Ahi + (bm + ar) * (size_t)lda + as * 8;
    const __nv_bfloat16* gAl = Alo + (bm + ar) * (size_t)lda + as * 8;
    const __nv_bfloat16* gWh = Whi + (size_t)br * ldw + bn + bs * 8;
    const __nv_bfloat16* gWl = Wlo + (size_t)br * ldw + bn + bs * 8;
    const uint32_t sAo = ar * PA + as * 16;
    const uint32_t sBo = br * PB + bs * 16;

    // ---- compute mapping: 16 warps = 4(m) x 4(n); warp tile 32x64 ----
    const int wid = tid >> 5, lane = tid & 31;
    const int wm = (wid >> 2) * 32;
    const int wn = (wid & 3) * 64;
    const uint32_t aA = (wm + (lane & 15)) * PA + (lane >> 4) * 16;
    const uint32_t bA = (lane & 15) * PB + (wn + (lane >> 4) * 8) * 2;

    float acc[2][8][4];
#pragma unroll
    for (int a = 0; a < 2; a++)
#pragma unroll
        for (int b = 0; b < 8; b++)
#pragma unroll
            for (int c = 0; c < 4; c++) acc[a][b][c] = 0.f;

    const int NKT = K / 32;

    auto load_stage = [&](int st, int k0) {
        const uint32_t s = sb + st * STAGE;
        CP_ASYNC(s + sAo,                        gAh + k0);
        CP_ASYNC(s + ASZ + sAo,                  gAl + k0);
        const size_t wko = (size_t)k0 * ldw;
        CP_ASYNC(s + 2 * ASZ + sBo,              gWh + wko);
        CP_ASYNC(s + 2 * ASZ + sBo + 256,        gWh + wko + 128);
        CP_ASYNC(s + 2 * ASZ + BSZ + sBo,        gWl + wko);
        CP_ASYNC(s + 2 * ASZ + BSZ + sBo + 256,  gWl + wko + 128);
        CP_COMMIT();
    };

    load_stage(0, 0);
    load_stage(1, 32);

    for (int kt = 0; kt < NKT; kt++) {
        if (kt + 1 < NKT) { CP_WAIT(1); } else { CP_WAIT(0); }
        __syncthreads();

        const int st = kt % NSTAGE;
        const uint32_t sA  = sb + st * STAGE;
        const uint32_t sAl = sA + ASZ;
        const uint32_t sB  = sA + 2 * ASZ;
        const uint32_t sBl = sB + BSZ;

#pragma unroll
        for (int ks = 0; ks < 32; ks += 16) {
            uint32_t ah[2][4], al[2][4];
#pragma unroll
            for (int mt = 0; mt < 2; mt++) {
                ldsm_x4(ah[mt], sA  + aA + mt * 16 * PA + ks * 2);
                ldsm_x4(al[mt], sAl + aA + mt * 16 * PA + ks * 2);
            }
#pragma unroll
            for (int nt = 0; nt < 4; nt++) {
                uint32_t bh[4], bl[4];
                ldsm_x4_t(bh, sB  + bA + nt * 32 + ks * PB);
                ldsm_x4_t(bl, sBl + bA + nt * 32 + ks * PB);
#pragma unroll
                for (int mt = 0; mt < 2; mt++)
#pragma unroll
                    for (int nb = 0; nb < 2; nb++) {
                        float* C = acc[mt][nt * 2 + nb];
                        mma_bf16(C, ah[mt], &bh[nb * 2]);
                        mma_bf16(C, al[mt], &bh[nb * 2]);
                        mma_bf16(C, ah[mt], &bl[nb * 2]);
                    }
            }
        }

        if (kt + 2 < NKT) load_stage((kt + 2) % NSTAGE, (kt + 2) * 32);
    }

    // ---- epilogue ----
    const int g = lane >> 2, t4 = lane & 3;
#pragma unroll
    for (int mt = 0; mt < 2; mt++)
#pragma unroll
        for (int half = 0; half < 2; half++) {
            const size_t row = bm + wm + mt * 16 + g + half * 8;
#pragma unroll
            for (int j = 0; j < 8; j++) {
                const int col = bn + wn + j * 8 + t4 * 2;
                float x = acc[mt][j][half * 2 + 0] + __ldg(&bias[col]);
                float y = acc[mt][j][half * 2 + 1] + __ldg(&bias[col + 1]);
                if (MODE == 0) {
                    x = tanhf(x);
                    y = tanhf(y);
                    __nv_bfloat162 hb = __float22bfloat162_rn(make_float2(x, y));
                    float rx = x - __bfloat162float(hb.x);
                    float ry = y - __bfloat162float(hb.y);
                    __nv_bfloat162 lb = __float22bfloat162_rn(make_float2(rx, ry));
                    *(__nv_bfloat162*)&Hhi[row * 1024 + col] = hb;
                    *(__nv_bfloat162*)&Hlo[row * 1024 + col] = lb;
                } else {
                    *(float2*)&P[row * 512 + poff + col] = make_float2(x, y);
                }
            }
        }
}

// ===========================================================================
// Final assembly: one warp per batch row.
// ===========================================================================
__global__ void __launch_bounds__(256)
epilogue_kernel(const float* __restrict__ z, const float* __restrict__ P,
                const float* __restrict__ inv_mass, const float* __restrict__ diffusion,
                float* __restrict__ out)
{
    const int warp = threadIdx.x >> 5;
    const int lane = threadIdx.x & 31;
    const size_t b = (size_t)blockIdx.x * 8 + warp;
    if (b >= BATCH) return;

    const float* prow = P + b * 512;
    float* drift = out + b * 513;
    float* dout = out + (size_t)BATCH * 513 + b * 513;

    float local = 0.f;
#pragma unroll
    for (int jj = 0; jj < 8; jj++) {
        const int n = jj * 32 + lane;
        const float post = prow[n];
        const float prior = prow[256 + n];
        const float d = diffusion[n];
        const float sgn = (d > 0.f) ? 1.f : ((d < 0.f) ? -1.f : 0.f);
        const float sd = (fabsf(d) > 1e-7f) ? d : sgn * 1e-7f;
        const float q = (prior - post) / sd;
        local += q * q;

        drift[n] = inv_mass[n] * z[b * 513 + 256 + n];
        drift[256 + n] = post;
        dout[n] = 0.f;
        dout[256 + n] = d;
    }
#pragma unroll
    for (int o = 16; o; o >>= 1) local += __shfl_xor_sync(0xffffffffu, local, o);
    if (lane == 0) { drift[512] = local; dout[512] = 0.f; }
}

// ===========================================================================
extern "C" void kernel_launch(void* const* d_in, const int* in_sizes, int n_in,
                              void* d_out, int out_size) {
    const float* z         = (const float*)d_in[0];
    const float* ts        = (const float*)d_in[1];
    const float* tp        = (const float*)d_in[2];
    const float* ctx       = (const float*)d_in[3];
    const float* inv_mass  = (const float*)d_in[4];
    const float* diffusion = (const float*)d_in[5];
    const float* Wc1 = (const float*)d_in[6];
    const float* bc1 = (const float*)d_in[7];
    const float* Wc2 = (const float*)d_in[8];
    const float* bc2 = (const float*)d_in[9];
    const float* Wh1 = (const float*)d_in[10];
    const float* bh1 = (const float*)d_in[11];
    const float* Wh2 = (const float*)d_in[12];
    const float* bh2 = (const float*)d_in[13];
    float* out = (float*)d_out;

    __nv_bfloat16 *Ah, *Al, *Hh, *Hl, *Wh, *Wl;
    float* gP;
    cudaGetSymbolAddress((void**)&Ah, g_A_hi);
    cudaGetSymbolAddress((void**)&Al, g_A_lo);
    cudaGetSymbolAddress((void**)&Hh, g_H_hi);
    cudaGetSymbolAddress((void**)&Hl, g_H_lo);
    cudaGetSymbolAddress((void**)&Wh, g_W_hi);
    cudaGetSymbolAddress((void**)&Wl, g_W_lo);
    cudaGetSymbolAddress((void**)&gP, g_P);
    const size_t HO = (size_t)BATCH * 1024;

    static bool attr_done = false;
    if (!attr_done) {
        cudaFuncSetAttribute(gemm_mma<0>, cudaFuncAttributeMaxDynamicSharedMemorySize, SMEMB);
        cudaFuncSetAttribute(gemm_mma<1>, cudaFuncAttributeMaxDynamicSharedMemorySize, SMEMB);
        attr_done = true;
    }

    // ---- prep ----
    prep_A<<<(BATCH * 1024) / 256, 256>>>(z, ctx, ts, tp, Ah, Al);
    prep_W<<<(1024 * 1024) / 256, 256>>>(Wc1, 1024 * 1024, Wh + WOFF_C1, Wl + WOFF_C1);
    prep_W<<<(512 * 1024) / 256, 256>>>(Wh1, 512 * 1024, Wh + WOFF_H1, Wl + WOFF_H1);
    prep_W<<<(1024 * 256) / 256, 256>>>(Wc2, 1024 * 256, Wh + WOFF_C2, Wl + WOFF_C2);
    prep_W<<<(1024 * 256) / 256, 256>>>(Wh2, 1024 * 256, Wh + WOFF_H2, Wl + WOFF_H2);

    // ---- GEMMs ----
    dim3 g1(4, BATCH / 128);   // N=1024 -> 4 tiles of 256
    dim3 g2(1, BATCH / 128);   // N=256  -> 1 tile

    // L1 post: Hpost = tanh([z|ctx] @ Wc1 + bc1), K=1024
    gemm_mma<0><<<g1, 512, SMEMB>>>(Ah, Al, 1024, 1024, Wh + WOFF_C1, Wl + WOFF_C1, 1024,
                                    bc1, Hh, Hl, nullptr, 0);
    // L1 prior: Hprior = tanh(z @ Wh1 + bh1), K=512 (first 512 cols of A buffer)
    gemm_mma<0><<<g1, 512, SMEMB>>>(Ah, Al, 1024, 512, Wh + WOFF_H1, Wl + WOFF_H1, 1024,
                                    bh1, Hh + HO, Hl + HO, nullptr, 0);
    // L2 post: P[:, :256] = Hpost @ Wc2 + bc2
    gemm_mma<1><<<g2, 512, SMEMB>>>(Hh, Hl, 1024, 1024, Wh + WOFF_C2, Wl + WOFF_C2, 256,
                                    bc2, nullptr, nullptr, gP, 0);
    // L2 prior: P[:, 256:] = Hprior @ Wh2 + bh2
    gemm_mma<1><<<g2, 512, SMEMB>>>(Hh + HO, Hl + HO, 1024, 1024, Wh + WOFF_H2, Wl + WOFF_H2, 256,
                                    bh2, nullptr, nullptr, gP, 256);

    // ---- output assembly ----
    epilogue_kernel<<<BATCH / 8, 256>>>(z, gP, inv_mass, diffusion, out);
}